// round 11
// baseline (speedup 1.0000x reference)
#include <cuda_runtime.h>
#include <math.h>
#include <stdint.h>

// ---------------- problem constants ----------------
#define B_ 2
#define N_ 384
#define D_ 256
#define H_ 8
#define DH_ 32
#define PD_ 64
#define L_ 8
#define ROWS_ (B_*N_)      // 768
#define FF_ 1024
#define FEAT_ 320          // D + PD

// ---------------- scratch buffers ----------------
__device__ __align__(16) float g_x   [ROWS_*D_];
__device__ __align__(16) float g_tmp [ROWS_*D_];
__device__ __align__(16) float g_h   [ROWS_*D_];
__device__ __align__(16) float g_qkv [3*ROWS_*D_];
__device__ __align__(16) float g_ao  [ROWS_*D_];
__device__ __align__(16) float g_ffn [ROWS_*FF_];
__device__ __align__(16) float g_s   [16*384*384];
__device__ __align__(16) float g_proj[ROWS_*PD_];
__device__ __align__(16) float g_pm  [ROWS_*PD_];
__device__ __align__(16) float g_u   [ROWS_*128];
__device__ __align__(16) float g_t   [ROWS_*3];

// ---------------- reductions ----------------
__device__ __forceinline__ float2 block_sum2_256(float a, float b) {
    __shared__ float sa[8], sb[8];
    int lane = threadIdx.x & 31, wid = threadIdx.x >> 5;
#pragma unroll
    for (int o = 16; o > 0; o >>= 1) {
        a += __shfl_xor_sync(0xffffffffu, a, o);
        b += __shfl_xor_sync(0xffffffffu, b, o);
    }
    if (lane == 0) { sa[wid] = a; sb[wid] = b; }
    __syncthreads();
    if (threadIdx.x == 0) {
        float A = sa[0], Bv = sb[0];
        for (int w = 1; w < 8; w++) { A += sa[w]; Bv += sb[w]; }
        sa[0] = A; sb[0] = Bv;
    }
    __syncthreads();
    float2 r = make_float2(sa[0], sb[0]);
    __syncthreads();
    return r;
}

// ---------------- embedding + pos-enc + layernorm ----------------
__global__ void embed_kernel(const int* __restrict__ tokens,
                             const float* __restrict__ tok_emb,
                             const float* __restrict__ w,
                             const float* __restrict__ b,
                             float* __restrict__ out) {
    int row = blockIdx.x;
    int n = row % N_;
    int c = threadIdx.x;
    int tok = tokens[row];
    float val = tok_emb[tok * D_ + c];
    int half = c >> 1;
    float div = expf((float)(2 * half) * (-9.210340371976184f / (float)D_));
    float ang = (float)n * div;
    val += (c & 1) ? cosf(ang) : sinf(ang);
    float2 s = block_sum2_256(val, val * val);
    float m = s.x * (1.f / D_);
    float var = s.y * (1.f / D_) - m * m;
    out[row * D_ + c] = (val - m) * rsqrtf(var + 1e-5f) * w[c] + b[c];
}

// ---------------- dual layernorm ----------------
__global__ void ln2_kernel(const float* __restrict__ in,
                           const float* __restrict__ w1, const float* __restrict__ b1,
                           const float* __restrict__ w2, const float* __restrict__ b2,
                           float* __restrict__ xo, float* __restrict__ ho) {
    int row = blockIdx.x;
    int c = threadIdx.x;
    float v = in[row * D_ + c];
    float2 s = block_sum2_256(v, v * v);
    float m = s.x * (1.f / D_);
    float var = s.y * (1.f / D_) - m * m;
    float x1 = (v - m) * rsqrtf(var + 1e-5f) * w1[c] + b1[c];
    xo[row * D_ + c] = x1;
    float2 s2 = block_sum2_256(x1, x1 * x1);
    float m2 = s2.x * (1.f / D_);
    float var2 = s2.y * (1.f / D_) - m2 * m2;
    ho[row * D_ + c] = (x1 - m2) * rsqrtf(var2 + 1e-5f) * w2[c] + b2[c];
}

// ---------------- tf32 helpers ----------------
__device__ __forceinline__ float f2tf32(float f) {
    uint32_t r;
    asm("cvt.rna.tf32.f32 %0, %1;" : "=r"(r) : "f"(f));
    return __uint_as_float(r);
}
__device__ __forceinline__ void mma_tf32(float c[4],
        uint32_t a0, uint32_t a1, uint32_t a2, uint32_t a3,
        uint32_t b0, uint32_t b1) {
    asm volatile(
        "mma.sync.aligned.m16n8k8.row.col.f32.tf32.tf32.f32 "
        "{%0,%1,%2,%3}, {%4,%5,%6,%7}, {%8,%9}, {%0,%1,%2,%3};"
        : "+f"(c[0]), "+f"(c[1]), "+f"(c[2]), "+f"(c[3])
        : "r"(a0), "r"(a1), "r"(a2), "r"(a3), "r"(b0), "r"(b1));
}

// ============ gemm_tc: TF32 tensor-core GEMM ============
template<int M, int N, int K, int TM, int TN, int WM, int ACT, bool RES>
__global__ __launch_bounds__(128) void gemm_tc(
    const float* __restrict__ A, const float* __restrict__ B,
    const float* __restrict__ bias, const float* __restrict__ res,
    float* __restrict__ C) {
    constexpr int S = K / 16;
    constexpr int PA = TM + 4, PB = TN + 4;
    constexpr int CG = 4 / WM;
    constexpr int NSUB = TN / CG;
    constexpr int NT = NSUB / 8;
    constexpr int A4 = TM * 4;
    constexpr int AL = (A4 + 127) / 128;
    constexpr int B4 = TN * 4;
    constexpr int BL = (B4 + 127) / 128;

    __shared__ float As[2][16][PA];
    __shared__ float Bs[2][16][PB];

    int t = threadIdx.x, lane = t & 31, wid = t >> 5;
    int g = lane >> 2, tg = lane & 3;
    int warp_m = wid % WM, warp_n = wid / WM;
    int m0 = blockIdx.y * TM, n0 = blockIdx.x * TN;
    int mb = warp_m * 16, nb = warp_n * NSUB;

    float4 pa[AL], pb[BL];
    auto loadA = [&](int s) {
#pragma unroll
        for (int u = 0; u < AL; u++) {
            int f = t + u * 128;
            if ((A4 % 128) && f >= A4) break;
            int ar = f >> 2, ak = (f & 3) * 4;
            pa[u] = *(const float4*)&A[(size_t)(m0 + ar) * K + s * 16 + ak];
        }
    };
    auto storeA = [&](int buf) {
#pragma unroll
        for (int u = 0; u < AL; u++) {
            int f = t + u * 128;
            if ((A4 % 128) && f >= A4) break;
            int ar = f >> 2, ak = (f & 3) * 4;
            As[buf][ak + 0][ar] = f2tf32(pa[u].x);
            As[buf][ak + 1][ar] = f2tf32(pa[u].y);
            As[buf][ak + 2][ar] = f2tf32(pa[u].z);
            As[buf][ak + 3][ar] = f2tf32(pa[u].w);
        }
    };
    auto loadB = [&](int s) {
#pragma unroll
        for (int u = 0; u < BL; u++) {
            int f = t + u * 128;
            if ((B4 % 128) && f >= B4) break;
            int br = f / (TN / 4), bc = (f % (TN / 4)) * 4;
            pb[u] = *(const float4*)&B[(size_t)(s * 16 + br) * N + n0 + bc];
        }
    };
    auto storeB = [&](int buf) {
#pragma unroll
        for (int u = 0; u < BL; u++) {
            int f = t + u * 128;
            if ((B4 % 128) && f >= B4) break;
            int br = f / (TN / 4), bc = (f % (TN / 4)) * 4;
            float4 cv = make_float4(f2tf32(pb[u].x), f2tf32(pb[u].y),
                                    f2tf32(pb[u].z), f2tf32(pb[u].w));
            *(float4*)&Bs[buf][br][bc] = cv;
        }
    };

    loadA(0); loadB(0);
    storeA(0); storeB(0);
    __syncthreads();

    float acc[NT][4];
#pragma unroll
    for (int i = 0; i < NT; i++)
#pragma unroll
        for (int j = 0; j < 4; j++) acc[i][j] = 0.f;

#pragma unroll 1
    for (int s = 0; s < S; s++) {
        int buf = s & 1;
        if (s + 1 < S) { loadA(s + 1); loadB(s + 1); }
#pragma unroll
        for (int ko = 0; ko < 16; ko += 8) {
            uint32_t a0 = __float_as_uint(As[buf][ko + tg][mb + g]);
            uint32_t a1 = __float_as_uint(As[buf][ko + tg][mb + g + 8]);
            uint32_t a2 = __float_as_uint(As[buf][ko + tg + 4][mb + g]);
            uint32_t a3 = __float_as_uint(As[buf][ko + tg + 4][mb + g + 8]);
#pragma unroll
            for (int nt = 0; nt < NT; nt++) {
                uint32_t b0 = __float_as_uint(Bs[buf][ko + tg][nb + nt * 8 + g]);
                uint32_t b1 = __float_as_uint(Bs[buf][ko + tg + 4][nb + nt * 8 + g]);
                mma_tf32(acc[nt], a0, a1, a2, a3, b0, b1);
            }
        }
        if (s + 1 < S) { storeA((s + 1) & 1); storeB((s + 1) & 1); }
        __syncthreads();
    }

    int r0 = m0 + mb + g, r1 = r0 + 8;
#pragma unroll
    for (int nt = 0; nt < NT; nt++) {
        int col = n0 + nb + nt * 8 + tg * 2;
        float v0 = acc[nt][0], v1 = acc[nt][1], v2 = acc[nt][2], v3 = acc[nt][3];
        if (bias) { float bb0 = bias[col], bb1 = bias[col + 1]; v0 += bb0; v1 += bb1; v2 += bb0; v3 += bb1; }
        if (RES) {
            v0 += res[(size_t)r0 * N + col]; v1 += res[(size_t)r0 * N + col + 1];
            v2 += res[(size_t)r1 * N + col]; v3 += res[(size_t)r1 * N + col + 1];
        }
        if (ACT == 2) {
            v0 = 0.5f * v0 * (1.f + erff(v0 * 0.7071067811865475f));
            v1 = 0.5f * v1 * (1.f + erff(v1 * 0.7071067811865475f));
            v2 = 0.5f * v2 * (1.f + erff(v2 * 0.7071067811865475f));
            v3 = 0.5f * v3 * (1.f + erff(v3 * 0.7071067811865475f));
        }
        *(float2*)&C[(size_t)r0 * N + col] = make_float2(v0, v1);
        *(float2*)&C[(size_t)r1 * N + col] = make_float2(v2, v3);
    }
}

// ============ gemm8: fp32, 128 threads, 64x128 tile (scores) ============
template<int M, int N, int K, int ACT, int MODE>
__global__ __launch_bounds__(128) void gemm8(
    const float* __restrict__ Abase, const float* __restrict__ Bb0,
    const float* __restrict__ Bb1,   const float* __restrict__ Bb2,
    const float* __restrict__ bias,  float* __restrict__ Cbase) {
    constexpr int TM = 64, TN = 128;
    constexpr int S = K / 16;

    __shared__ alignas(16) float As[2][16][TM];
    __shared__ alignas(16) float Bs[2][16][TN];

    int t = threadIdx.x;
    int tx = t & 15, ty = t >> 4;
    int m0 = blockIdx.y * TM, n0 = blockIdx.x * TN;
    int z = blockIdx.z;

    const float* A; const float* Bp; float* C;
    int lda, ldb, ldc;
    if (MODE == 0) { A = Abase; Bp = Bb0; C = Cbase; lda = K; ldb = N; ldc = N; }
    else if (MODE == 1) {
        A = Abase; Bp = (z == 0) ? Bb0 : (z == 1) ? Bb1 : Bb2;
        C = Cbase + (size_t)z * M * N; lda = K; ldb = N; ldc = N;
    } else {
        int bidx = z >> 3; int h = z & 7;
        A  = Abase + (size_t)bidx * N_ * D_ + h * DH_;
        Bp = Bb0   + (size_t)bidx * N_ * D_ + h * DH_;
        C  = Cbase + (size_t)z * M * N;
        lda = D_; ldb = D_; ldc = N;
    }

    float4 pa[2], pb[4];
    auto loadA = [&](int s) {
#pragma unroll
        for (int u = 0; u < 2; u++) {
            int f = t + u * 128;
            int ar = f >> 2, ak = (f & 3) * 4;
            pa[u] = *(const float4*)&A[(size_t)(m0 + ar) * lda + s * 16 + ak];
        }
    };
    auto storeA = [&](int buf) {
#pragma unroll
        for (int u = 0; u < 2; u++) {
            int f = t + u * 128;
            int ar = f >> 2, ak = (f & 3) * 4;
            As[buf][ak + 0][ar] = pa[u].x; As[buf][ak + 1][ar] = pa[u].y;
            As[buf][ak + 2][ar] = pa[u].z; As[buf][ak + 3][ar] = pa[u].w;
        }
    };
    auto loadB = [&](int s) {
#pragma unroll
        for (int u = 0; u < 4; u++) {
            int f = t + u * 128;
            if (MODE == 2) {
                int br = f >> 2, bk = (f & 3) * 4;
                pb[u] = *(const float4*)&Bp[(size_t)(n0 + br) * ldb + s * 16 + bk];
            } else {
                int br = f >> 5, bc = (f & 31) * 4;
                pb[u] = *(const float4*)&Bp[(size_t)(s * 16 + br) * ldb + n0 + bc];
            }
        }
    };
    auto storeB = [&](int buf) {
#pragma unroll
        for (int u = 0; u < 4; u++) {
            int f = t + u * 128;
            if (MODE == 2) {
                int br = f >> 2, bk = (f & 3) * 4;
                Bs[buf][bk + 0][br] = pb[u].x; Bs[buf][bk + 1][br] = pb[u].y;
                Bs[buf][bk + 2][br] = pb[u].z; Bs[buf][bk + 3][br] = pb[u].w;
            } else {
                int br = f >> 5, bc = (f & 31) * 4;
                *(float4*)&Bs[buf][br][bc] = pb[u];
            }
        }
    };

    loadA(0); loadB(0);
    storeA(0); storeB(0);
    __syncthreads();

    float acc[8][8];
#pragma unroll
    for (int i = 0; i < 8; i++)
#pragma unroll
        for (int j = 0; j < 8; j++) acc[i][j] = 0.f;

#pragma unroll 1
    for (int s = 0; s < S; s++) {
        int buf = s & 1;
        if (s + 1 < S) { loadA(s + 1); loadB(s + 1); }
#pragma unroll
        for (int k = 0; k < 16; k++) {
            float4 a0 = *(float4*)&As[buf][k][ty * 8];
            float4 a1 = *(float4*)&As[buf][k][ty * 8 + 4];
            float4 b0 = *(float4*)&Bs[buf][k][tx * 8];
            float4 b1 = *(float4*)&Bs[buf][k][tx * 8 + 4];
            float ra[8] = {a0.x, a0.y, a0.z, a0.w, a1.x, a1.y, a1.z, a1.w};
            float rb[8] = {b0.x, b0.y, b0.z, b0.w, b1.x, b1.y, b1.z, b1.w};
#pragma unroll
            for (int i = 0; i < 8; i++)
#pragma unroll
                for (int j = 0; j < 8; j++) acc[i][j] = fmaf(ra[i], rb[j], acc[i][j]);
        }
        if (s + 1 < S) { storeA((s + 1) & 1); storeB((s + 1) & 1); }
        __syncthreads();
    }

#pragma unroll
    for (int i = 0; i < 8; i++) {
        int m = m0 + ty * 8 + i;
#pragma unroll
        for (int j = 0; j < 8; j++) {
            int n = n0 + tx * 8 + j;
            float v = acc[i][j];
            if (MODE == 2) v *= 0.17677669529663687f;
            if (bias) v += bias[n];
            if (ACT == 2) v = 0.5f * v * (1.f + erff(v * 0.7071067811865475f));
            acc[i][j] = v;
        }
        float4* dst = (float4*)&C[(size_t)m * ldc + n0 + tx * 8];
        dst[0] = make_float4(acc[i][0], acc[i][1], acc[i][2], acc[i][3]);
        dst[1] = make_float4(acc[i][4], acc[i][5], acc[i][6], acc[i][7]);
    }
}

// ---------------- legacy GEMM ----------------
// MODE 0: plain; MODE 1: QKV batched; MODE 4: concat [x|pm]
template<int M, int N, int K, int TM, int TN, int ACT, bool RES, int MODE>
__global__ __launch_bounds__(256) void gemm_k(
    const float* __restrict__ Abase, const float* __restrict__ Bb0,
    const float* __restrict__ Bb1,   const float* __restrict__ Bb2,
    const float* __restrict__ bias,  const float* __restrict__ res,
    float* __restrict__ Cbase) {
    constexpr int TX = TN / 4;
    constexpr int TY = 256 / TX;
    constexpr int RM = TM / TY;
    constexpr int S  = K / 16;
    constexpr int A4TOT = TM * 4;
    constexpr int ALOOP = (A4TOT + 255) / 256;
    constexpr int B4TOT = TN * 4;
    constexpr int BLOOP = (B4TOT + 255) / 256;

    __shared__ alignas(16) float As[2][16][TM];
    __shared__ alignas(16) float Bs[2][16][TN];

    int t = threadIdx.x;
    int m0 = blockIdx.y * TM, n0 = blockIdx.x * TN;
    int z = blockIdx.z;

    const float* A; const float* Bp; float* C;
    if (MODE == 1) {
        A = Abase; Bp = (z == 0) ? Bb0 : (z == 1) ? Bb1 : Bb2;
        C = Cbase + (size_t)z * M * N;
    } else { A = Abase; Bp = Bb0; C = Cbase; }

    int tx = t % TX, ty = t / TX;

    float4 pa[ALOOP], pb[BLOOP];
    auto loadA = [&](int s) {
#pragma unroll
        for (int u = 0; u < ALOOP; u++) {
            int f = t + u * 256;
            if ((A4TOT % 256) && f >= A4TOT) break;
            int ar = f >> 2, ak = (f & 3) * 4;
            int col = s * 16 + ak;
            if (MODE == 4) {
                const float* src = (col < 256)
                    ? &Abase[(size_t)(m0 + ar) * 256 + col]
                    : &Bb1[(size_t)(m0 + ar) * 64 + (col - 256)];
                pa[u] = *(const float4*)src;
            } else {
                pa[u] = *(const float4*)&A[(size_t)(m0 + ar) * K + col];
            }
        }
    };
    auto storeA = [&](int buf) {
#pragma unroll
        for (int u = 0; u < ALOOP; u++) {
            int f = t + u * 256;
            if ((A4TOT % 256) && f >= A4TOT) break;
            int ar = f >> 2, ak = (f & 3) * 4;
            As[buf][ak + 0][ar] = pa[u].x; As[buf][ak + 1][ar] = pa[u].y;
            As[buf][ak + 2][ar] = pa[u].z; As[buf][ak + 3][ar] = pa[u].w;
        }
    };
    auto loadB = [&](int s) {
#pragma unroll
        for (int u = 0; u < BLOOP; u++) {
            int f = t + u * 256;
            if ((B4TOT % 256) && f >= B4TOT) break;
            int br = f / TX, bc = (f % TX) * 4;
            pb[u] = *(const float4*)&Bp[(size_t)(s * 16 + br) * N + n0 + bc];
        }
    };
    auto storeB = [&](int buf) {
#pragma unroll
        for (int u = 0; u < BLOOP; u++) {
            int f = t + u * 256;
            if ((B4TOT % 256) && f >= B4TOT) break;
            int br = f / TX, bc = (f % TX) * 4;
            *(float4*)&Bs[buf][br][bc] = pb[u];
        }
    };

    loadA(0); loadB(0);
    storeA(0); storeB(0);
    __syncthreads();

    float acc[RM][4];
#pragma unroll
    for (int i = 0; i < RM; i++)
#pragma unroll
        for (int j = 0; j < 4; j++) acc[i][j] = 0.f;

#pragma unroll 2
    for (int s = 0; s < S; s++) {
        int buf = s & 1;
        if (s + 1 < S) { loadA(s + 1); loadB(s + 1); }
#pragma unroll
        for (int k = 0; k < 16; k++) {
            float rb[4];
#pragma unroll
            for (int j = 0; j < 4; j++) rb[j] = Bs[buf][k][tx * 4 + j];
            float ra[RM];
#pragma unroll
            for (int i = 0; i < RM; i++) ra[i] = As[buf][k][ty * RM + i];
#pragma unroll
            for (int i = 0; i < RM; i++)
#pragma unroll
                for (int j = 0; j < 4; j++) acc[i][j] = fmaf(ra[i], rb[j], acc[i][j]);
        }
        if (s + 1 < S) { storeA((s + 1) & 1); storeB((s + 1) & 1); }
        __syncthreads();
    }

#pragma unroll
    for (int i = 0; i < RM; i++) {
        int m = m0 + ty * RM + i;
#pragma unroll
        for (int j = 0; j < 4; j++) {
            int n = n0 + tx * 4 + j;
            float v = acc[i][j];
            if (bias) v += bias[n];
            if (RES) v += res[(size_t)m * N + n];
            if (ACT == 1) v = fmaxf(v, 0.f);
            else if (ACT == 2) v = 0.5f * v * (1.f + erff(v * 0.7071067811865475f));
            else if (ACT == 3) v = v / (1.f + __expf(-v));
            C[(size_t)m * N + n] = v;
        }
    }
}

// ============ fused softmax(-d2) + AV ============
// grid (1, 12, 16): y = 32-row i-tile, z = b*8+h. 256 threads.
// Pass 1: per-row softmax (with -d2 bias) into smem Ps[32][385].
// Pass 2: rank-1-update AV from smem probs + L1-broadcast V rows.
#define AVSM_FLOATS (32*385 + 384*3 + 32*3)
__global__ __launch_bounds__(256) void avsm_kernel(
        const float* __restrict__ S, const float* __restrict__ V,
        const float* __restrict__ tb, float* __restrict__ ao) {
    extern __shared__ float sm[];
    float* Ps = sm;                   // [32][385]
    float* tj = sm + 32 * 385;        // [384*3]
    float* ti = tj + 384 * 3;         // [32*3]

    int t = threadIdx.x, lane = t & 31, w = t >> 5;
    int m0 = blockIdx.y * 32;
    int z = blockIdx.z;
    int b = z >> 3, h = z & 7;
    const float* tbb = tb + (size_t)b * N_ * 3;

    for (int q = t; q < 384 * 3; q += 256) tj[q] = tbb[q];
    for (int q = t; q < 32 * 3; q += 256) ti[q] = tbb[m0 * 3 + q];
    __syncthreads();

    // pass 1: softmax rows (warp w handles rows 4w..4w+3)
#pragma unroll
    for (int rr = 0; rr < 4; rr++) {
        int r = w * 4 + rr;
        int i = m0 + r;
        const float* row = S + ((size_t)z * 384 + i) * 384;
        float tix = ti[r * 3], tiy = ti[r * 3 + 1], tiz = ti[r * 3 + 2];
        float v[12];
        float mx = -1e30f;
#pragma unroll
        for (int q = 0; q < 12; q++) {
            int j = lane + q * 32;
            float dx = tix - tj[j * 3], dy = tiy - tj[j * 3 + 1], dz = tiz - tj[j * 3 + 2];
            v[q] = row[j] - (dx * dx + dy * dy + dz * dz);
            mx = fmaxf(mx, v[q]);
        }
#pragma unroll
        for (int o = 16; o > 0; o >>= 1) mx = fmaxf(mx, __shfl_xor_sync(0xffffffffu, mx, o));
        float s = 0.f;
#pragma unroll
        for (int q = 0; q < 12; q++) { v[q] = __expf(v[q] - mx); s += v[q]; }
#pragma unroll
        for (int o = 16; o > 0; o >>= 1) s += __shfl_xor_sync(0xffffffffu, s, o);
        float inv = 1.f / s;
#pragma unroll
        for (int q = 0; q < 12; q++) Ps[r * 385 + lane + q * 32] = v[q] * inv;
    }
    __syncthreads();

    // pass 2: AV. thread = (i=lane, d-quad=w). V row broadcast via L1.
    int d4 = w * 4;
    const float* Vb = V + (size_t)b * N_ * D_ + h * DH_ + d4;
    const float* Pr = Ps + lane * 385;
    float4 acc = make_float4(0.f, 0.f, 0.f, 0.f);
#pragma unroll 4
    for (int j = 0; j < 384; j++) {
        float p = Pr[j];
        float4 vv = *(const float4*)&Vb[(size_t)j * D_];
        acc.x = fmaf(p, vv.x, acc.x);
        acc.y = fmaf(p, vv.y, acc.y);
        acc.z = fmaf(p, vv.z, acc.z);
        acc.w = fmaf(p, vv.w, acc.w);
    }
    *(float4*)&ao[((size_t)(b * N_ + m0 + lane)) * D_ + h * DH_ + d4] = acc;
}

// ---------------- fused pair LN + mean ----------------
__global__ __launch_bounds__(512) void pair_kernel(
        const float* __restrict__ proj, const float* __restrict__ relpos,
        const float* __restrict__ pw, const float* __restrict__ pb,
        float* __restrict__ pm) {
    int row = blockIdx.x;
    int b = row / N_, i = row % N_;
    int t = threadIdx.x;
    int w = t >> 5, l = t & 31;

    __shared__ float pi[PD_];
    __shared__ float accs[16][PD_];

    if (t < PD_) pi[t] = proj[row * PD_ + t];
    __syncthreads();

    float w0 = pw[l], w1 = pw[l + 32], bb0 = pb[l], bb1 = pb[l + 32];
    float p0 = pi[l], p1 = pi[l + 32];
    float a0 = 0.f, a1 = 0.f;
    for (int j = w; j < N_; j += 16) {
        int rel = min(64, max(-64, j - i)) + 64;
        const float* pj = proj + (size_t)(b * N_ + j) * PD_;
        const float* re = relpos + (size_t)rel * PD_;
        float v0 = p0 + pj[l] + re[l];
        float v1 = p1 + pj[l + 32] + re[l + 32];
        float s = v0 + v1, s2 = v0 * v0 + v1 * v1;
#pragma unroll
        for (int o = 16; o > 0; o >>= 1) {
            s  += __shfl_xor_sync(0xffffffffu, s, o);
            s2 += __shfl_xor_sync(0xffffffffu, s2, o);
        }
        float m = s * (1.f / PD_);
        float var = s2 * (1.f / PD_) - m * m;
        float rs = rsqrtf(var + 1e-5f);
        a0 += (v0 - m) * rs * w0 + bb0;
        a1 += (v1 - m) * rs * w1 + bb1;
    }
    accs[w][l] = a0; accs[w][l + 32] = a1;
    __syncthreads();
    if (t < PD_) {
        float s = 0.f;
#pragma unroll
        for (int ww = 0; ww < 16; ww++) s += accs[ww][t];
        pm[row * PD_ + t] = s * (1.f / N_);
    }
}

// ---------------- frames ----------------
__global__ void frame_kernel(const float* __restrict__ u, const float* __restrict__ Wf2,
                             const float* __restrict__ bf2,
                             float* __restrict__ frames, float* __restrict__ tb) {
    int row = blockIdx.x;
    int t = threadIdx.x;
    __shared__ float us[128];
    __shared__ float raw[9];
    us[t] = u[row * 128 + t];
    __syncthreads();
    if (t < 9) {
        float s = bf2[t];
        for (int k = 0; k < 128; k++) s += us[k] * Wf2[k * 9 + t];
        raw[t] = s;
    }
    __syncthreads();
    if (t == 0) {
        float a1x = raw[0], a1y = raw[1], a1z = raw[2];
        float a2x = raw[3], a2y = raw[4], a2z = raw[5];
        float n1 = sqrtf(a1x * a1x + a1y * a1y + a1z * a1z + 1e-8f);
        float b1x = a1x / n1, b1y = a1y / n1, b1z = a1z / n1;
        float d = b1x * a2x + b1y * a2y + b1z * a2z;
        float px = a2x - d * b1x, py = a2y - d * b1y, pz = a2z - d * b1z;
        float n2 = sqrtf(px * px + py * py + pz * pz + 1e-8f);
        float b2x = px / n2, b2y = py / n2, b2z = pz / n2;
        float b3x = b1y * b2z - b1z * b2y;
        float b3y = b1z * b2x - b1x * b2z;
        float b3z = b1x * b2y - b1y * b2x;
        float tx = raw[6], ty = raw[7], tz = raw[8];
        float* F = frames + (size_t)row * 16;
        F[0] = b1x; F[1] = b1y; F[2]  = b1z; F[3]  = tx;
        F[4] = b2x; F[5] = b2y; F[6]  = b2z; F[7]  = ty;
        F[8] = b3x; F[9] = b3y; F[10] = b3z; F[11] = tz;
        F[12] = 0.f; F[13] = 0.f; F[14] = 0.f; F[15] = 1.f;
        tb[row * 3 + 0] = tx; tb[row * 3 + 1] = ty; tb[row * 3 + 2] = tz;
    }
}

// ---------------- utility ----------------
__global__ void zero_kernel(float* p, int n) {
    int i = blockIdx.x * blockDim.x + threadIdx.x;
    if (i < n) p[i] = 0.f;
}
__global__ void copy_kernel(const float* __restrict__ src, float* __restrict__ dst) {
    dst[blockIdx.x * blockDim.x + threadIdx.x] = src[blockIdx.x * blockDim.x + threadIdx.x];
}

// ---------------- host ----------------
extern "C" void kernel_launch(void* const* d_in, const int* in_sizes, int n_in,
                              void* d_out, int out_size) {
    (void)in_sizes; (void)n_in; (void)out_size;
    const int*   tokens     = (const int*)d_in[0];
    const float* tok_emb    = (const float*)d_in[1];
    const float* emb_ln_w   = (const float*)d_in[2];
    const float* emb_ln_b   = (const float*)d_in[3];
    const float* Wq         = (const float*)d_in[4];
    const float* Wk         = (const float*)d_in[5];
    const float* Wv         = (const float*)d_in[6];
    const float* Wo         = (const float*)d_in[7];
    const float* bo         = (const float*)d_in[8];
    const float* attn_ln_w  = (const float*)d_in[9];
    const float* attn_ln_b  = (const float*)d_in[10];
    const float* ff_ln_w    = (const float*)d_in[11];
    const float* ff_ln_b    = (const float*)d_in[12];
    const float* W1         = (const float*)d_in[13];
    const float* b1         = (const float*)d_in[14];
    const float* W2         = (const float*)d_in[15];
    const float* b2         = (const float*)d_in[16];
    const float* Wop        = (const float*)d_in[17];
    const float* bop        = (const float*)d_in[18];
    const float* relpos     = (const float*)d_in[19];
    const float* pair_ln_w  = (const float*)d_in[20];
    const float* pair_ln_b  = (const float*)d_in[21];
    const float* Wf1        = (const float*)d_in[22];
    const float* bf1        = (const float*)d_in[23];
    const float* Wf2        = (const float*)d_in[24];
    const float* bf2        = (const float*)d_in[25];

    float *x, *tmp, *h, *qkv, *ao, *ffn, *sbuf, *proj, *pm, *u, *tb;
    cudaGetSymbolAddress((void**)&x,   g_x);
    cudaGetSymbolAddress((void**)&tmp, g_tmp);
    cudaGetSymbolAddress((void**)&h,   g_h);
    cudaGetSymbolAddress((void**)&qkv, g_qkv);
    cudaGetSymbolAddress((void**)&ao,  g_ao);
    cudaGetSymbolAddress((void**)&ffn, g_ffn);
    cudaGetSymbolAddress((void**)&sbuf,g_s);
    cudaGetSymbolAddress((void**)&proj,g_proj);
    cudaGetSymbolAddress((void**)&pm,  g_pm);
    cudaGetSymbolAddress((void**)&u,   g_u);
    cudaGetSymbolAddress((void**)&tb,  g_t);

    float* q = qkv;
    float* k = qkv + (size_t)ROWS_ * D_;
    float* v = qkv + (size_t)2 * ROWS_ * D_;

    float* fout = (float*)d_out;
    float* xout = fout + ROWS_ * 16;

    static cudaStream_t sside = nullptr;
    static cudaEvent_t  evp[40];
    if (sside == nullptr) {
        cudaStreamCreateWithFlags(&sside, cudaStreamNonBlocking);
        for (int i = 0; i < 40; i++)
            cudaEventCreateWithFlags(&evp[i], cudaEventDisableTiming);
        cudaFuncSetAttribute(avsm_kernel,
            cudaFuncAttributeMaxDynamicSharedMemorySize, AVSM_FLOATS * 4);
    }
    int evi = 0;

    zero_kernel<<<(ROWS_ * 3 + 255) / 256, 256>>>(tb, ROWS_ * 3);
    embed_kernel<<<ROWS_, 256>>>(tokens, tok_emb, emb_ln_w, emb_ln_b, x);

    // layer-0 QKV + raw scores
    gemm_k<ROWS_, D_, D_, 64, 64, 0, false, 1>
        <<<dim3(4, 12, 3), 256>>>(x, Wq, Wk, Wv, nullptr, nullptr, qkv);
    gemm8<384, 384, 32, 0, 2>
        <<<dim3(3, 6, 16), 128>>>(q, k, nullptr, nullptr, nullptr, sbuf);

    for (int l = 0; l < L_; l++) {
        const float* Wol = Wo + (size_t)l * D_ * D_;
        const float* bol = bo + (size_t)l * D_;
        const float* W1l = W1 + (size_t)l * D_ * FF_;
        const float* b1l = b1 + (size_t)l * FF_;
        const float* W2l = W2 + (size_t)l * FF_ * D_;
        const float* b2l = b2 + (size_t)l * D_;

        // fused softmax(-d2) + AV
        avsm_kernel<<<dim3(1, 12, 16), 256, AVSM_FLOATS * 4>>>(sbuf, v, tb, ao);

        // tmp = x + ao@Wo + bo
        gemm_k<ROWS_, D_, D_, 32, 64, 0, true, 0>
            <<<dim3(4, 24), 256>>>(ao, Wol, nullptr, nullptr, bol, x, tmp);
        // x = LN1(tmp); h = LN2(x)
        ln2_kernel<<<ROWS_, 256>>>(tmp, attn_ln_w + l * D_, attn_ln_b + l * D_,
                                   ff_ln_w + l * D_, ff_ln_b + l * D_, x, h);

        // FFN on TF32 tensor cores
        gemm_tc<ROWS_, FF_, D_, 64, 64, 4, 2, false>
            <<<dim3(16, 12), 128>>>(h, W1l, b1l, nullptr, ffn);
        gemm_tc<ROWS_, D_, FF_, 32, 64, 2, 0, true>
            <<<dim3(4, 24), 128>>>(ffn, W2l, b2l, x, x);

        // fork: frame chain on side stream
        cudaEvent_t eFork = evp[evi++];
        cudaEventRecord(eFork, 0);
        cudaStreamWaitEvent(sside, eFork, 0);

        gemm_k<ROWS_, PD_, D_, 32, 64, 1, false, 0>
            <<<dim3(1, 24), 256, 0, sside>>>(x, Wop, nullptr, nullptr, bop, nullptr, proj);
        pair_kernel<<<ROWS_, 512, 0, sside>>>(proj, relpos, pair_ln_w, pair_ln_b, pm);
        gemm_k<ROWS_, 128, FEAT_, 32, 64, 3, false, 4>
            <<<dim3(2, 24), 256, 0, sside>>>(x, Wf1, pm, nullptr, bf1, nullptr, u);
        frame_kernel<<<ROWS_, 128, 0, sside>>>(u, Wf2, bf2, fout, tb);

        cudaEvent_t eJoin = evp[evi++];
        cudaEventRecord(eJoin, sside);

        // main stream overlap: next layer's QKV + raw scores
        if (l + 1 < L_) {
            gemm_k<ROWS_, D_, D_, 64, 64, 0, false, 1>
                <<<dim3(4, 12, 3), 256>>>(x,
                    Wq + (size_t)(l + 1) * D_ * D_,
                    Wk + (size_t)(l + 1) * D_ * D_,
                    Wv + (size_t)(l + 1) * D_ * D_, nullptr, nullptr, qkv);
            gemm8<384, 384, 32, 0, 2>
                <<<dim3(3, 6, 16), 128>>>(q, k, nullptr, nullptr, nullptr, sbuf);
        }

        cudaStreamWaitEvent(0, eJoin, 0);
    }

    copy_kernel<<<ROWS_, 256>>>(x, xout);
}

// round 12
// speedup vs baseline: 1.1272x; 1.1272x over previous
#include <cuda_runtime.h>
#include <math.h>
#include <stdint.h>

// ---------------- problem constants ----------------
#define B_ 2
#define N_ 384
#define D_ 256
#define H_ 8
#define DH_ 32
#define PD_ 64
#define L_ 8
#define ROWS_ (B_*N_)      // 768
#define FF_ 1024
#define FEAT_ 320          // D + PD

// ---------------- scratch buffers ----------------
__device__ __align__(16) float g_x   [ROWS_*D_];
__device__ __align__(16) float g_tmp [ROWS_*D_];
__device__ __align__(16) float g_h   [ROWS_*D_];
__device__ __align__(16) float g_qkv [3*ROWS_*D_];
__device__ __align__(16) float g_ao  [ROWS_*D_];
__device__ __align__(16) float g_ffn [ROWS_*FF_];
__device__ __align__(16) float g_s   [16*384*384];
__device__ __align__(16) float g_proj[ROWS_*PD_];
__device__ __align__(16) float g_pm  [ROWS_*PD_];
__device__ __align__(16) float g_u   [ROWS_*128];
__device__ __align__(16) float g_t   [ROWS_*3];

// ---------------- reductions ----------------
__device__ __forceinline__ float2 block_sum2_256(float a, float b) {
    __shared__ float sa[8], sb[8];
    int lane = threadIdx.x & 31, wid = threadIdx.x >> 5;
#pragma unroll
    for (int o = 16; o > 0; o >>= 1) {
        a += __shfl_xor_sync(0xffffffffu, a, o);
        b += __shfl_xor_sync(0xffffffffu, b, o);
    }
    if (lane == 0) { sa[wid] = a; sb[wid] = b; }
    __syncthreads();
    if (threadIdx.x == 0) {
        float A = sa[0], Bv = sb[0];
        for (int w = 1; w < 8; w++) { A += sa[w]; Bv += sb[w]; }
        sa[0] = A; sb[0] = Bv;
    }
    __syncthreads();
    float2 r = make_float2(sa[0], sb[0]);
    __syncthreads();
    return r;
}

// ---------------- embedding + pos-enc + layernorm ----------------
__global__ void embed_kernel(const int* __restrict__ tokens,
                             const float* __restrict__ tok_emb,
                             const float* __restrict__ w,
                             const float* __restrict__ b,
                             float* __restrict__ out) {
    int row = blockIdx.x;
    int n = row % N_;
    int c = threadIdx.x;
    int tok = tokens[row];
    float val = tok_emb[tok * D_ + c];
    int half = c >> 1;
    float div = expf((float)(2 * half) * (-9.210340371976184f / (float)D_));
    float ang = (float)n * div;
    val += (c & 1) ? cosf(ang) : sinf(ang);
    float2 s = block_sum2_256(val, val * val);
    float m = s.x * (1.f / D_);
    float var = s.y * (1.f / D_) - m * m;
    out[row * D_ + c] = (val - m) * rsqrtf(var + 1e-5f) * w[c] + b[c];
}

// ---------------- dual layernorm ----------------
__global__ void ln2_kernel(const float* __restrict__ in,
                           const float* __restrict__ w1, const float* __restrict__ b1,
                           const float* __restrict__ w2, const float* __restrict__ b2,
                           float* __restrict__ xo, float* __restrict__ ho) {
    int row = blockIdx.x;
    int c = threadIdx.x;
    float v = in[row * D_ + c];
    float2 s = block_sum2_256(v, v * v);
    float m = s.x * (1.f / D_);
    float var = s.y * (1.f / D_) - m * m;
    float x1 = (v - m) * rsqrtf(var + 1e-5f) * w1[c] + b1[c];
    xo[row * D_ + c] = x1;
    float2 s2 = block_sum2_256(x1, x1 * x1);
    float m2 = s2.x * (1.f / D_);
    float var2 = s2.y * (1.f / D_) - m2 * m2;
    ho[row * D_ + c] = (x1 - m2) * rsqrtf(var2 + 1e-5f) * w2[c] + b2[c];
}

// ---------------- tf32 helpers ----------------
__device__ __forceinline__ float f2tf32(float f) {
    uint32_t r;
    asm("cvt.rna.tf32.f32 %0, %1;" : "=r"(r) : "f"(f));
    return __uint_as_float(r);
}
__device__ __forceinline__ void mma_tf32(float c[4],
        uint32_t a0, uint32_t a1, uint32_t a2, uint32_t a3,
        uint32_t b0, uint32_t b1) {
    asm volatile(
        "mma.sync.aligned.m16n8k8.row.col.f32.tf32.tf32.f32 "
        "{%0,%1,%2,%3}, {%4,%5,%6,%7}, {%8,%9}, {%0,%1,%2,%3};"
        : "+f"(c[0]), "+f"(c[1]), "+f"(c[2]), "+f"(c[3])
        : "r"(a0), "r"(a1), "r"(a2), "r"(a3), "r"(b0), "r"(b1));
}

// ============ gemm_tc: TF32 tensor-core GEMM ============
template<int M, int N, int K, int TM, int TN, int WM, int ACT, bool RES>
__global__ __launch_bounds__(128) void gemm_tc(
    const float* __restrict__ A, const float* __restrict__ B,
    const float* __restrict__ bias, const float* __restrict__ res,
    float* __restrict__ C) {
    constexpr int S = K / 16;
    constexpr int PA = TM + 4, PB = TN + 4;
    constexpr int CG = 4 / WM;
    constexpr int NSUB = TN / CG;
    constexpr int NT = NSUB / 8;
    constexpr int A4 = TM * 4;
    constexpr int AL = (A4 + 127) / 128;
    constexpr int B4 = TN * 4;
    constexpr int BL = (B4 + 127) / 128;

    __shared__ float As[2][16][PA];
    __shared__ float Bs[2][16][PB];

    int t = threadIdx.x, lane = t & 31, wid = t >> 5;
    int g = lane >> 2, tg = lane & 3;
    int warp_m = wid % WM, warp_n = wid / WM;
    int m0 = blockIdx.y * TM, n0 = blockIdx.x * TN;
    int mb = warp_m * 16, nb = warp_n * NSUB;

    float4 pa[AL], pb[BL];
    auto loadA = [&](int s) {
#pragma unroll
        for (int u = 0; u < AL; u++) {
            int f = t + u * 128;
            if ((A4 % 128) && f >= A4) break;
            int ar = f >> 2, ak = (f & 3) * 4;
            pa[u] = *(const float4*)&A[(size_t)(m0 + ar) * K + s * 16 + ak];
        }
    };
    auto storeA = [&](int buf) {
#pragma unroll
        for (int u = 0; u < AL; u++) {
            int f = t + u * 128;
            if ((A4 % 128) && f >= A4) break;
            int ar = f >> 2, ak = (f & 3) * 4;
            As[buf][ak + 0][ar] = f2tf32(pa[u].x);
            As[buf][ak + 1][ar] = f2tf32(pa[u].y);
            As[buf][ak + 2][ar] = f2tf32(pa[u].z);
            As[buf][ak + 3][ar] = f2tf32(pa[u].w);
        }
    };
    auto loadB = [&](int s) {
#pragma unroll
        for (int u = 0; u < BL; u++) {
            int f = t + u * 128;
            if ((B4 % 128) && f >= B4) break;
            int br = f / (TN / 4), bc = (f % (TN / 4)) * 4;
            pb[u] = *(const float4*)&B[(size_t)(s * 16 + br) * N + n0 + bc];
        }
    };
    auto storeB = [&](int buf) {
#pragma unroll
        for (int u = 0; u < BL; u++) {
            int f = t + u * 128;
            if ((B4 % 128) && f >= B4) break;
            int br = f / (TN / 4), bc = (f % (TN / 4)) * 4;
            float4 cv = make_float4(f2tf32(pb[u].x), f2tf32(pb[u].y),
                                    f2tf32(pb[u].z), f2tf32(pb[u].w));
            *(float4*)&Bs[buf][br][bc] = cv;
        }
    };

    loadA(0); loadB(0);
    storeA(0); storeB(0);
    __syncthreads();

    float acc[NT][4];
#pragma unroll
    for (int i = 0; i < NT; i++)
#pragma unroll
        for (int j = 0; j < 4; j++) acc[i][j] = 0.f;

#pragma unroll 1
    for (int s = 0; s < S; s++) {
        int buf = s & 1;
        if (s + 1 < S) { loadA(s + 1); loadB(s + 1); }
#pragma unroll
        for (int ko = 0; ko < 16; ko += 8) {
            uint32_t a0 = __float_as_uint(As[buf][ko + tg][mb + g]);
            uint32_t a1 = __float_as_uint(As[buf][ko + tg][mb + g + 8]);
            uint32_t a2 = __float_as_uint(As[buf][ko + tg + 4][mb + g]);
            uint32_t a3 = __float_as_uint(As[buf][ko + tg + 4][mb + g + 8]);
#pragma unroll
            for (int nt = 0; nt < NT; nt++) {
                uint32_t b0 = __float_as_uint(Bs[buf][ko + tg][nb + nt * 8 + g]);
                uint32_t b1 = __float_as_uint(Bs[buf][ko + tg + 4][nb + nt * 8 + g]);
                mma_tf32(acc[nt], a0, a1, a2, a3, b0, b1);
            }
        }
        if (s + 1 < S) { storeA((s + 1) & 1); storeB((s + 1) & 1); }
        __syncthreads();
    }

    int r0 = m0 + mb + g, r1 = r0 + 8;
#pragma unroll
    for (int nt = 0; nt < NT; nt++) {
        int col = n0 + nb + nt * 8 + tg * 2;
        float v0 = acc[nt][0], v1 = acc[nt][1], v2 = acc[nt][2], v3 = acc[nt][3];
        if (bias) { float bb0 = bias[col], bb1 = bias[col + 1]; v0 += bb0; v1 += bb1; v2 += bb0; v3 += bb1; }
        if (RES) {
            v0 += res[(size_t)r0 * N + col]; v1 += res[(size_t)r0 * N + col + 1];
            v2 += res[(size_t)r1 * N + col]; v3 += res[(size_t)r1 * N + col + 1];
        }
        if (ACT == 2) {
            v0 = 0.5f * v0 * (1.f + erff(v0 * 0.7071067811865475f));
            v1 = 0.5f * v1 * (1.f + erff(v1 * 0.7071067811865475f));
            v2 = 0.5f * v2 * (1.f + erff(v2 * 0.7071067811865475f));
            v3 = 0.5f * v3 * (1.f + erff(v3 * 0.7071067811865475f));
        }
        *(float2*)&C[(size_t)r0 * N + col] = make_float2(v0, v1);
        *(float2*)&C[(size_t)r1 * N + col] = make_float2(v2, v3);
    }
}

// ============ gemm8: fp32, 128 threads, 64x128 tile (scores) ============
template<int M, int N, int K, int ACT, int MODE>
__global__ __launch_bounds__(128) void gemm8(
    const float* __restrict__ Abase, const float* __restrict__ Bb0,
    const float* __restrict__ Bb1,   const float* __restrict__ Bb2,
    const float* __restrict__ bias,  float* __restrict__ Cbase) {
    constexpr int TM = 64, TN = 128;
    constexpr int S = K / 16;

    __shared__ alignas(16) float As[2][16][TM];
    __shared__ alignas(16) float Bs[2][16][TN];

    int t = threadIdx.x;
    int tx = t & 15, ty = t >> 4;
    int m0 = blockIdx.y * TM, n0 = blockIdx.x * TN;
    int z = blockIdx.z;

    const float* A; const float* Bp; float* C;
    int lda, ldb, ldc;
    if (MODE == 0) { A = Abase; Bp = Bb0; C = Cbase; lda = K; ldb = N; ldc = N; }
    else if (MODE == 1) {
        A = Abase; Bp = (z == 0) ? Bb0 : (z == 1) ? Bb1 : Bb2;
        C = Cbase + (size_t)z * M * N; lda = K; ldb = N; ldc = N;
    } else {
        int bidx = z >> 3; int h = z & 7;
        A  = Abase + (size_t)bidx * N_ * D_ + h * DH_;
        Bp = Bb0   + (size_t)bidx * N_ * D_ + h * DH_;
        C  = Cbase + (size_t)z * M * N;
        lda = D_; ldb = D_; ldc = N;
    }

    float4 pa[2], pb[4];
    auto loadA = [&](int s) {
#pragma unroll
        for (int u = 0; u < 2; u++) {
            int f = t + u * 128;
            int ar = f >> 2, ak = (f & 3) * 4;
            pa[u] = *(const float4*)&A[(size_t)(m0 + ar) * lda + s * 16 + ak];
        }
    };
    auto storeA = [&](int buf) {
#pragma unroll
        for (int u = 0; u < 2; u++) {
            int f = t + u * 128;
            int ar = f >> 2, ak = (f & 3) * 4;
            As[buf][ak + 0][ar] = pa[u].x; As[buf][ak + 1][ar] = pa[u].y;
            As[buf][ak + 2][ar] = pa[u].z; As[buf][ak + 3][ar] = pa[u].w;
        }
    };
    auto loadB = [&](int s) {
#pragma unroll
        for (int u = 0; u < 4; u++) {
            int f = t + u * 128;
            if (MODE == 2) {
                int br = f >> 2, bk = (f & 3) * 4;
                pb[u] = *(const float4*)&Bp[(size_t)(n0 + br) * ldb + s * 16 + bk];
            } else {
                int br = f >> 5, bc = (f & 31) * 4;
                pb[u] = *(const float4*)&Bp[(size_t)(s * 16 + br) * ldb + n0 + bc];
            }
        }
    };
    auto storeB = [&](int buf) {
#pragma unroll
        for (int u = 0; u < 4; u++) {
            int f = t + u * 128;
            if (MODE == 2) {
                int br = f >> 2, bk = (f & 3) * 4;
                Bs[buf][bk + 0][br] = pb[u].x; Bs[buf][bk + 1][br] = pb[u].y;
                Bs[buf][bk + 2][br] = pb[u].z; Bs[buf][bk + 3][br] = pb[u].w;
            } else {
                int br = f >> 5, bc = (f & 31) * 4;
                *(float4*)&Bs[buf][br][bc] = pb[u];
            }
        }
    };

    loadA(0); loadB(0);
    storeA(0); storeB(0);
    __syncthreads();

    float acc[8][8];
#pragma unroll
    for (int i = 0; i < 8; i++)
#pragma unroll
        for (int j = 0; j < 8; j++) acc[i][j] = 0.f;

#pragma unroll 1
    for (int s = 0; s < S; s++) {
        int buf = s & 1;
        if (s + 1 < S) { loadA(s + 1); loadB(s + 1); }
#pragma unroll
        for (int k = 0; k < 16; k++) {
            float4 a0 = *(float4*)&As[buf][k][ty * 8];
            float4 a1 = *(float4*)&As[buf][k][ty * 8 + 4];
            float4 b0 = *(float4*)&Bs[buf][k][tx * 8];
            float4 b1 = *(float4*)&Bs[buf][k][tx * 8 + 4];
            float ra[8] = {a0.x, a0.y, a0.z, a0.w, a1.x, a1.y, a1.z, a1.w};
            float rb[8] = {b0.x, b0.y, b0.z, b0.w, b1.x, b1.y, b1.z, b1.w};
#pragma unroll
            for (int i = 0; i < 8; i++)
#pragma unroll
                for (int j = 0; j < 8; j++) acc[i][j] = fmaf(ra[i], rb[j], acc[i][j]);
        }
        if (s + 1 < S) { storeA((s + 1) & 1); storeB((s + 1) & 1); }
        __syncthreads();
    }

#pragma unroll
    for (int i = 0; i < 8; i++) {
        int m = m0 + ty * 8 + i;
#pragma unroll
        for (int j = 0; j < 8; j++) {
            int n = n0 + tx * 8 + j;
            float v = acc[i][j];
            if (MODE == 2) v *= 0.17677669529663687f;
            if (bias) v += bias[n];
            if (ACT == 2) v = 0.5f * v * (1.f + erff(v * 0.7071067811865475f));
            acc[i][j] = v;
        }
        float4* dst = (float4*)&C[(size_t)m * ldc + n0 + tx * 8];
        dst[0] = make_float4(acc[i][0], acc[i][1], acc[i][2], acc[i][3]);
        dst[1] = make_float4(acc[i][4], acc[i][5], acc[i][6], acc[i][7]);
    }
}

// ---------------- legacy GEMM ----------------
// MODE 0: plain; MODE 1: QKV batched; MODE 3: AV; MODE 4: concat [x|pm]
template<int M, int N, int K, int TM, int TN, int ACT, bool RES, int MODE>
__global__ __launch_bounds__(256) void gemm_k(
    const float* __restrict__ Abase, const float* __restrict__ Bb0,
    const float* __restrict__ Bb1,   const float* __restrict__ Bb2,
    const float* __restrict__ bias,  const float* __restrict__ res,
    float* __restrict__ Cbase) {
    constexpr int TX = TN / 4;
    constexpr int TY = 256 / TX;
    constexpr int RM = TM / TY;
    constexpr int S  = K / 16;
    constexpr int A4TOT = TM * 4;
    constexpr int ALOOP = (A4TOT + 255) / 256;
    constexpr int B4TOT = TN * 4;
    constexpr int BLOOP = (B4TOT + 255) / 256;

    __shared__ alignas(16) float As[2][16][TM];
    __shared__ alignas(16) float Bs[2][16][TN];

    int t = threadIdx.x;
    int m0 = blockIdx.y * TM, n0 = blockIdx.x * TN;
    int z = blockIdx.z;

    const float* A; const float* Bp; float* C;
    int lda, ldb, ldc;
    if (MODE == 0 || MODE == 4) { A = Abase; Bp = Bb0; C = Cbase; lda = K; ldb = N; ldc = N; }
    else if (MODE == 1) {
        A = Abase; Bp = (z == 0) ? Bb0 : (z == 1) ? Bb1 : Bb2;
        C = Cbase + (size_t)z * M * N; lda = K; ldb = N; ldc = N;
    } else {
        int bidx = z >> 3; int h = z & 7;
        A  = Abase + (size_t)z * M * K;
        Bp = Bb0   + (size_t)bidx * N_ * D_ + h * DH_;
        C  = Cbase + (size_t)bidx * N_ * D_ + h * DH_;
        lda = K; ldb = D_; ldc = D_;
    }

    int tx = t % TX, ty = t / TX;

    float4 pa[ALOOP], pb[BLOOP];
    auto loadA = [&](int s) {
#pragma unroll
        for (int u = 0; u < ALOOP; u++) {
            int f = t + u * 256;
            if ((A4TOT % 256) && f >= A4TOT) break;
            int ar = f >> 2, ak = (f & 3) * 4;
            int col = s * 16 + ak;
            if (MODE == 4) {
                const float* src = (col < 256)
                    ? &Abase[(size_t)(m0 + ar) * 256 + col]
                    : &Bb1[(size_t)(m0 + ar) * 64 + (col - 256)];
                pa[u] = *(const float4*)src;
            } else {
                pa[u] = *(const float4*)&A[(size_t)(m0 + ar) * lda + col];
            }
        }
    };
    auto storeA = [&](int buf) {
#pragma unroll
        for (int u = 0; u < ALOOP; u++) {
            int f = t + u * 256;
            if ((A4TOT % 256) && f >= A4TOT) break;
            int ar = f >> 2, ak = (f & 3) * 4;
            As[buf][ak + 0][ar] = pa[u].x; As[buf][ak + 1][ar] = pa[u].y;
            As[buf][ak + 2][ar] = pa[u].z; As[buf][ak + 3][ar] = pa[u].w;
        }
    };
    auto loadB = [&](int s) {
#pragma unroll
        for (int u = 0; u < BLOOP; u++) {
            int f = t + u * 256;
            if ((B4TOT % 256) && f >= B4TOT) break;
            int br = f / TX, bc = (f % TX) * 4;
            pb[u] = *(const float4*)&Bp[(size_t)(s * 16 + br) * ldb + n0 + bc];
        }
    };
    auto storeB = [&](int buf) {
#pragma unroll
        for (int u = 0; u < BLOOP; u++) {
            int f = t + u * 256;
            if ((B4TOT % 256) && f >= B4TOT) break;
            int br = f / TX, bc = (f % TX) * 4;
            *(float4*)&Bs[buf][br][bc] = pb[u];
        }
    };

    loadA(0); loadB(0);
    storeA(0); storeB(0);
    __syncthreads();

    float acc[RM][4];
#pragma unroll
    for (int i = 0; i < RM; i++)
#pragma unroll
        for (int j = 0; j < 4; j++) acc[i][j] = 0.f;

#pragma unroll 2
    for (int s = 0; s < S; s++) {
        int buf = s & 1;
        if (s + 1 < S) { loadA(s + 1); loadB(s + 1); }
#pragma unroll
        for (int k = 0; k < 16; k++) {
            float rb[4];
#pragma unroll
            for (int j = 0; j < 4; j++) rb[j] = Bs[buf][k][tx * 4 + j];
            float ra[RM];
#pragma unroll
            for (int i = 0; i < RM; i++) ra[i] = As[buf][k][ty * RM + i];
#pragma unroll
            for (int i = 0; i < RM; i++)
#pragma unroll
                for (int j = 0; j < 4; j++) acc[i][j] = fmaf(ra[i], rb[j], acc[i][j]);
        }
        if (s + 1 < S) { storeA((s + 1) & 1); storeB((s + 1) & 1); }
        __syncthreads();
    }

#pragma unroll
    for (int i = 0; i < RM; i++) {
        int m = m0 + ty * RM + i;
#pragma unroll
        for (int j = 0; j < 4; j++) {
            int n = n0 + tx * 4 + j;
            float v = acc[i][j];
            if (bias) v += bias[n];
            if (RES) v += res[(size_t)m * ldc + n];
            if (ACT == 1) v = fmaxf(v, 0.f);
            else if (ACT == 2) v = 0.5f * v * (1.f + erff(v * 0.7071067811865475f));
            else if (ACT == 3) v = v / (1.f + __expf(-v));
            C[(size_t)m * ldc + n] = v;
        }
    }
}

// ---------------- softmax with fused -d2 bias ----------------
__global__ void softmax_bias_kernel(float* __restrict__ S, const float* __restrict__ tb) {
    int r = blockIdx.x * 8 + (threadIdx.x >> 5);
    int l = threadIdx.x & 31;
    int z = r / 384, i = r - z * 384;
    int b = z >> 3;
    const float* tbb = tb + (size_t)b * N_ * 3;
    float tix = tbb[i * 3], tiy = tbb[i * 3 + 1], tiz = tbb[i * 3 + 2];
    float* row = S + (size_t)r * 384;
    float v[12];
    float mx = -1e30f;
#pragma unroll
    for (int q = 0; q < 12; q++) {
        int j = l + q * 32;
        float dx = tix - tbb[j * 3], dy = tiy - tbb[j * 3 + 1], dz = tiz - tbb[j * 3 + 2];
        v[q] = row[j] - (dx * dx + dy * dy + dz * dz);
        mx = fmaxf(mx, v[q]);
    }
#pragma unroll
    for (int o = 16; o > 0; o >>= 1) mx = fmaxf(mx, __shfl_xor_sync(0xffffffffu, mx, o));
    float s = 0.f;
#pragma unroll
    for (int q = 0; q < 12; q++) { v[q] = __expf(v[q] - mx); s += v[q]; }
#pragma unroll
    for (int o = 16; o > 0; o >>= 1) s += __shfl_xor_sync(0xffffffffu, s, o);
    float inv = 1.f / s;
#pragma unroll
    for (int q = 0; q < 12; q++) row[l + q * 32] = v[q] * inv;
}

// ---------------- fused pair LN + mean ----------------
__global__ __launch_bounds__(512) void pair_kernel(
        const float* __restrict__ proj, const float* __restrict__ relpos,
        const float* __restrict__ pw, const float* __restrict__ pb,
        float* __restrict__ pm) {
    int row = blockIdx.x;
    int b = row / N_, i = row % N_;
    int t = threadIdx.x;
    int w = t >> 5, l = t & 31;

    __shared__ float pi[PD_];
    __shared__ float accs[16][PD_];

    if (t < PD_) pi[t] = proj[row * PD_ + t];
    __syncthreads();

    float w0 = pw[l], w1 = pw[l + 32], bb0 = pb[l], bb1 = pb[l + 32];
    float p0 = pi[l], p1 = pi[l + 32];
    float a0 = 0.f, a1 = 0.f;
    for (int j = w; j < N_; j += 16) {
        int rel = min(64, max(-64, j - i)) + 64;
        const float* pj = proj + (size_t)(b * N_ + j) * PD_;
        const float* re = relpos + (size_t)rel * PD_;
        float v0 = p0 + pj[l] + re[l];
        float v1 = p1 + pj[l + 32] + re[l + 32];
        float s = v0 + v1, s2 = v0 * v0 + v1 * v1;
#pragma unroll
        for (int o = 16; o > 0; o >>= 1) {
            s  += __shfl_xor_sync(0xffffffffu, s, o);
            s2 += __shfl_xor_sync(0xffffffffu, s2, o);
        }
        float m = s * (1.f / PD_);
        float var = s2 * (1.f / PD_) - m * m;
        float rs = rsqrtf(var + 1e-5f);
        a0 += (v0 - m) * rs * w0 + bb0;
        a1 += (v1 - m) * rs * w1 + bb1;
    }
    accs[w][l] = a0; accs[w][l + 32] = a1;
    __syncthreads();
    if (t < PD_) {
        float s = 0.f;
#pragma unroll
        for (int ww = 0; ww < 16; ww++) s += accs[ww][t];
        pm[row * PD_ + t] = s * (1.f / N_);
    }
}

// ---------------- frames ----------------
__global__ void frame_kernel(const float* __restrict__ u, const float* __restrict__ Wf2,
                             const float* __restrict__ bf2,
                             float* __restrict__ frames, float* __restrict__ tb) {
    int row = blockIdx.x;
    int t = threadIdx.x;
    __shared__ float us[128];
    __shared__ float raw[9];
    us[t] = u[row * 128 + t];
    __syncthreads();
    if (t < 9) {
        float s = bf2[t];
        for (int k = 0; k < 128; k++) s += us[k] * Wf2[k * 9 + t];
        raw[t] = s;
    }
    __syncthreads();
    if (t == 0) {
        float a1x = raw[0], a1y = raw[1], a1z = raw[2];
        float a2x = raw[3], a2y = raw[4], a2z = raw[5];
        float n1 = sqrtf(a1x * a1x + a1y * a1y + a1z * a1z + 1e-8f);
        float b1x = a1x / n1, b1y = a1y / n1, b1z = a1z / n1;
        float d = b1x * a2x + b1y * a2y + b1z * a2z;
        float px = a2x - d * b1x, py = a2y - d * b1y, pz = a2z - d * b1z;
        float n2 = sqrtf(px * px + py * py + pz * pz + 1e-8f);
        float b2x = px / n2, b2y = py / n2, b2z = pz / n2;
        float b3x = b1y * b2z - b1z * b2y;
        float b3y = b1z * b2x - b1x * b2z;
        float b3z = b1x * b2y - b1y * b2x;
        float tx = raw[6], ty = raw[7], tz = raw[8];
        float* F = frames + (size_t)row * 16;
        F[0] = b1x; F[1] = b1y; F[2]  = b1z; F[3]  = tx;
        F[4] = b2x; F[5] = b2y; F[6]  = b2z; F[7]  = ty;
        F[8] = b3x; F[9] = b3y; F[10] = b3z; F[11] = tz;
        F[12] = 0.f; F[13] = 0.f; F[14] = 0.f; F[15] = 1.f;
        tb[row * 3 + 0] = tx; tb[row * 3 + 1] = ty; tb[row * 3 + 2] = tz;
    }
}

// ---------------- utility ----------------
__global__ void zero_kernel(float* p, int n) {
    int i = blockIdx.x * blockDim.x + threadIdx.x;
    if (i < n) p[i] = 0.f;
}
__global__ void copy_kernel(const float* __restrict__ src, float* __restrict__ dst) {
    dst[blockIdx.x * blockDim.x + threadIdx.x] = src[blockIdx.x * blockDim.x + threadIdx.x];
}

// ---------------- host ----------------
extern "C" void kernel_launch(void* const* d_in, const int* in_sizes, int n_in,
                              void* d_out, int out_size) {
    (void)in_sizes; (void)n_in; (void)out_size;
    const int*   tokens     = (const int*)d_in[0];
    const float* tok_emb    = (const float*)d_in[1];
    const float* emb_ln_w   = (const float*)d_in[2];
    const float* emb_ln_b   = (const float*)d_in[3];
    const float* Wq         = (const float*)d_in[4];
    const float* Wk         = (const float*)d_in[5];
    const float* Wv         = (const float*)d_in[6];
    const float* Wo         = (const float*)d_in[7];
    const float* bo         = (const float*)d_in[8];
    const float* attn_ln_w  = (const float*)d_in[9];
    const float* attn_ln_b  = (const float*)d_in[10];
    const float* ff_ln_w    = (const float*)d_in[11];
    const float* ff_ln_b    = (const float*)d_in[12];
    const float* W1         = (const float*)d_in[13];
    const float* b1         = (const float*)d_in[14];
    const float* W2         = (const float*)d_in[15];
    const float* b2         = (const float*)d_in[16];
    const float* Wop        = (const float*)d_in[17];
    const float* bop        = (const float*)d_in[18];
    const float* relpos     = (const float*)d_in[19];
    const float* pair_ln_w  = (const float*)d_in[20];
    const float* pair_ln_b  = (const float*)d_in[21];
    const float* Wf1        = (const float*)d_in[22];
    const float* bf1        = (const float*)d_in[23];
    const float* Wf2        = (const float*)d_in[24];
    const float* bf2        = (const float*)d_in[25];

    float *x, *tmp, *h, *qkv, *ao, *ffn, *sbuf, *proj, *pm, *u, *tb;
    cudaGetSymbolAddress((void**)&x,   g_x);
    cudaGetSymbolAddress((void**)&tmp, g_tmp);
    cudaGetSymbolAddress((void**)&h,   g_h);
    cudaGetSymbolAddress((void**)&qkv, g_qkv);
    cudaGetSymbolAddress((void**)&ao,  g_ao);
    cudaGetSymbolAddress((void**)&ffn, g_ffn);
    cudaGetSymbolAddress((void**)&sbuf,g_s);
    cudaGetSymbolAddress((void**)&proj,g_proj);
    cudaGetSymbolAddress((void**)&pm,  g_pm);
    cudaGetSymbolAddress((void**)&u,   g_u);
    cudaGetSymbolAddress((void**)&tb,  g_t);

    float* q = qkv;
    float* k = qkv + (size_t)ROWS_ * D_;
    float* v = qkv + (size_t)2 * ROWS_ * D_;

    float* fout = (float*)d_out;
    float* xout = fout + ROWS_ * 16;

    static cudaStream_t sside = nullptr;
    static cudaEvent_t  evp[40];
    if (sside == nullptr) {
        cudaStreamCreateWithFlags(&sside, cudaStreamNonBlocking);
        for (int i = 0; i < 40; i++)
            cudaEventCreateWithFlags(&evp[i], cudaEventDisableTiming);
    }
    int evi = 0;

    zero_kernel<<<(ROWS_ * 3 + 255) / 256, 256>>>(tb, ROWS_ * 3);
    embed_kernel<<<ROWS_, 256>>>(tokens, tok_emb, emb_ln_w, emb_ln_b, x);

    // layer-0 QKV + raw scores
    gemm_k<ROWS_, D_, D_, 64, 64, 0, false, 1>
        <<<dim3(4, 12, 3), 256>>>(x, Wq, Wk, Wv, nullptr, nullptr, qkv);
    gemm8<384, 384, 32, 0, 2>
        <<<dim3(3, 6, 16), 128>>>(q, k, nullptr, nullptr, nullptr, sbuf);

    for (int l = 0; l < L_; l++) {
        const float* Wol = Wo + (size_t)l * D_ * D_;
        const float* bol = bo + (size_t)l * D_;
        const float* W1l = W1 + (size_t)l * D_ * FF_;
        const float* b1l = b1 + (size_t)l * FF_;
        const float* W2l = W2 + (size_t)l * FF_ * D_;
        const float* b2l = b2 + (size_t)l * D_;

        // softmax with fused -d2 bias
        softmax_bias_kernel<<<768, 256>>>(sbuf, tb);

        // AV (smem-tiled gemm)
        gemm_k<384, 32, 384, 64, 32, 0, false, 3>
            <<<dim3(1, 6, 16), 256>>>(sbuf, v, nullptr, nullptr, nullptr, nullptr, ao);

        // tmp = x + ao@Wo + bo  (TF32 tensor cores)
        gemm_tc<ROWS_, D_, D_, 32, 64, 2, 0, true>
            <<<dim3(4, 24), 128>>>(ao, Wol, bol, x, tmp);
        // x = LN1(tmp); h = LN2(x)
        ln2_kernel<<<ROWS_, 256>>>(tmp, attn_ln_w + l * D_, attn_ln_b + l * D_,
                                   ff_ln_w + l * D_, ff_ln_b + l * D_, x, h);

        // FFN on TF32 tensor cores
        gemm_tc<ROWS_, FF_, D_, 64, 64, 4, 2, false>
            <<<dim3(16, 12), 128>>>(h, W1l, b1l, nullptr, ffn);
        gemm_tc<ROWS_, D_, FF_, 32, 64, 2, 0, true>
            <<<dim3(4, 24), 128>>>(ffn, W2l, b2l, x, x);

        // fork: frame chain on side stream
        cudaEvent_t eFork = evp[evi++];
        cudaEventRecord(eFork, 0);
        cudaStreamWaitEvent(sside, eFork, 0);

        gemm_k<ROWS_, PD_, D_, 32, 64, 1, false, 0>
            <<<dim3(1, 24), 256, 0, sside>>>(x, Wop, nullptr, nullptr, bop, nullptr, proj);
        pair_kernel<<<ROWS_, 512, 0, sside>>>(proj, relpos, pair_ln_w, pair_ln_b, pm);
        gemm_k<ROWS_, 128, FEAT_, 32, 64, 3, false, 4>
            <<<dim3(2, 24), 256, 0, sside>>>(x, Wf1, pm, nullptr, bf1, nullptr, u);
        frame_kernel<<<ROWS_, 128, 0, sside>>>(u, Wf2, bf2, fout, tb);

        cudaEvent_t eJoin = evp[evi++];
        cudaEventRecord(eJoin, sside);

        // main stream overlap: next layer's QKV + raw scores
        if (l + 1 < L_) {
            gemm_k<ROWS_, D_, D_, 64, 64, 0, false, 1>
                <<<dim3(4, 12, 3), 256>>>(x,
                    Wq + (size_t)(l + 1) * D_ * D_,
                    Wk + (size_t)(l + 1) * D_ * D_,
                    Wv + (size_t)(l + 1) * D_ * D_, nullptr, nullptr, qkv);
            gemm8<384, 384, 32, 0, 2>
                <<<dim3(3, 6, 16), 128>>>(q, k, nullptr, nullptr, nullptr, sbuf);
        }

        cudaStreamWaitEvent(0, eJoin, 0);
    }

    copy_kernel<<<ROWS_, 256>>>(x, xout);
}